// round 8
// baseline (speedup 1.0000x reference)
#include <cuda_runtime.h>
#include <cuda_fp16.h>

// DeformationGrid: trilinear interpolation of a [160,160,160,3] float grid
// at N=4194304 random points in the unit cube.
//
// R5 (resubmitted after infra failure): z-pair fp16 entries (4 LDG.128
// gathers/point, the layout optimum) + 2 points per thread so coords/out
// traffic is vectorized (LDG.64/STG.64, cutting ~13% of L1tex wavefronts)
// and gather MLP doubles. Streaming stores (__stcs) keep the 65.5MB grid
// resident in L2.

#define GRID_R 160
#define NVOX (GRID_R * GRID_R * GRID_R)   // 4,096,000

// 16B z-pair entry: halves [c0z0,c1z0, c2z0,c0z1, c1z1,c2z1, pad]
__device__ uint4 g_pair[NVOX];            // 65.5 MB scratch (.bss — allowed)

__device__ __forceinline__ unsigned h2_to_u32(__half2 h) {
    return *reinterpret_cast<unsigned*>(&h);
}
__device__ __forceinline__ __half2 u32_to_h2(unsigned u) {
    return *reinterpret_cast<__half2*>(&u);
}

// ---------------------------------------------------------------------------
// Repack: one block per (x,y) row of 160 z-voxels. Coalesced.
// ---------------------------------------------------------------------------
__global__ void __launch_bounds__(160)
repack_kernel(const float* __restrict__ theta)
{
    __shared__ float s[480];
    int row = blockIdx.x;                  // x*160 + y
    int t = threadIdx.x;                   // 0..159
    const float* src = theta + (size_t)row * 480;
    s[t]       = __ldg(src + t);
    s[t + 160] = __ldg(src + t + 160);
    s[t + 320] = __ldg(src + t + 320);
    __syncthreads();

    int z1 = min(t + 1, GRID_R - 1);       // z=159 entry: weight-0 duplicate
    uint4 e;
    e.x = h2_to_u32(__floats2half2_rn(s[3 * t + 0], s[3 * t + 1]));
    e.y = h2_to_u32(__floats2half2_rn(s[3 * t + 2], s[3 * z1 + 0]));
    e.z = h2_to_u32(__floats2half2_rn(s[3 * z1 + 1], s[3 * z1 + 2]));
    e.w = 0u;
    g_pair[(size_t)row * GRID_R + t] = e;
}

// ---------------------------------------------------------------------------
// Gather: 2 points per thread, 8 LDG.128 gathers in flight, fused lerps.
// ---------------------------------------------------------------------------
__device__ __forceinline__ float flerp(float a, float b, float t) {
    return fmaf(t, b - a, a);
}

struct PointIdx {
    int b00, b01, b10, b11;
    float fx, fy, fz;
};

__device__ __forceinline__ PointIdx make_idx(float cx, float cy, float cz)
{
    const float scale = (float)(GRID_R - 1);
    float px = cx * scale, py = cy * scale, pz = cz * scale;
    float fx0 = floorf(px), fy0 = floorf(py), fz0 = floorf(pz);
    PointIdx r;
    r.fx = px - fx0; r.fy = py - fy0; r.fz = pz - fz0;
    int ix = (int)fx0, iy = (int)fy0, iz = (int)fz0;
    ix = min(max(ix, 0), GRID_R - 1);
    iy = min(max(iy, 0), GRID_R - 1);
    iz = min(max(iz, 0), GRID_R - 1);
    int ix1 = min(ix + 1, GRID_R - 1);
    int iy1 = min(iy + 1, GRID_R - 1);
    const int SX = GRID_R * GRID_R, SY = GRID_R;
    r.b00 = ix  * SX + iy  * SY + iz;
    r.b01 = ix  * SX + iy1 * SY + iz;
    r.b10 = ix1 * SX + iy  * SY + iz;
    r.b11 = ix1 * SX + iy1 * SY + iz;
    return r;
}

__device__ __forceinline__ void zlerp_entry(uint4 e, float fz,
                                            float& r0, float& r1, float& r2)
{
    float2 p0 = __half22float2(u32_to_h2(e.x));   // (c0z0, c1z0)
    float2 p1 = __half22float2(u32_to_h2(e.y));   // (c2z0, c0z1)
    float2 p2 = __half22float2(u32_to_h2(e.z));   // (c1z1, c2z1)
    r0 = flerp(p0.x, p1.y, fz);
    r1 = flerp(p0.y, p2.x, fz);
    r2 = flerp(p1.x, p2.y, fz);
}

__device__ __forceinline__ void finish_point(const PointIdx& q,
                                             uint4 e00, uint4 e01, uint4 e10, uint4 e11,
                                             float& rx, float& ry, float& rz)
{
    float c00x, c00y, c00z, c01x, c01y, c01z;
    float c10x, c10y, c10z, c11x, c11y, c11z;
    zlerp_entry(e00, q.fz, c00x, c00y, c00z);
    zlerp_entry(e01, q.fz, c01x, c01y, c01z);
    zlerp_entry(e10, q.fz, c10x, c10y, c10z);
    zlerp_entry(e11, q.fz, c11x, c11y, c11z);
    float c0x = flerp(c00x, c01x, q.fy), c0y = flerp(c00y, c01y, q.fy), c0z = flerp(c00z, c01z, q.fy);
    float c1x = flerp(c10x, c11x, q.fy), c1y = flerp(c10y, c11y, q.fy), c1z = flerp(c10z, c11z, q.fy);
    rx = flerp(c0x, c1x, q.fx);
    ry = flerp(c0y, c1y, q.fx);
    rz = flerp(c0z, c1z, q.fx);
}

__global__ void __launch_bounds__(256)
trilerp_kernel(const float* __restrict__ coords,
               float* __restrict__ out,
               int n)
{
    int t = blockIdx.x * blockDim.x + threadIdx.x;
    int p = 2 * t;
    if (p >= n) return;

    // Coalesced coords load: floats [6t, 6t+6) as 3x float2.
    const float2* c2 = (const float2*)coords;
    float2 A = __ldg(c2 + 3 * t + 0);   // (x0, y0)
    float2 B = __ldg(c2 + 3 * t + 1);   // (z0, x1)
    float2 C = __ldg(c2 + 3 * t + 2);   // (y1, z1)

    PointIdx q0 = make_idx(A.x, A.y, B.x);
    PointIdx q1 = make_idx(B.y, C.x, C.y);

    // Issue all 8 gathers back-to-back for MLP.
    uint4 a00 = __ldg(g_pair + q0.b00);
    uint4 a01 = __ldg(g_pair + q0.b01);
    uint4 a10 = __ldg(g_pair + q0.b10);
    uint4 a11 = __ldg(g_pair + q0.b11);
    uint4 b00 = __ldg(g_pair + q1.b00);
    uint4 b01 = __ldg(g_pair + q1.b01);
    uint4 b10 = __ldg(g_pair + q1.b10);
    uint4 b11 = __ldg(g_pair + q1.b11);

    float r0x, r0y, r0z, r1x, r1y, r1z;
    finish_point(q0, a00, a01, a10, a11, r0x, r0y, r0z);
    finish_point(q1, b00, b01, b10, b11, r1x, r1y, r1z);

    // Coalesced streaming stores: 3x STG.64.
    float2* o2 = (float2*)out;
    if (p + 1 < n) {
        __stcs(o2 + 3 * t + 0, make_float2(r0x, r0y));
        __stcs(o2 + 3 * t + 1, make_float2(r0z, r1x));
        __stcs(o2 + 3 * t + 2, make_float2(r1y, r1z));
    } else {
        out[3 * p + 0] = r0x;
        out[3 * p + 1] = r0y;
        out[3 * p + 2] = r0z;
    }
}

extern "C" void kernel_launch(void* const* d_in, const int* in_sizes, int n_in,
                              void* d_out, int out_size) {
    const float* coords = (const float*)d_in[0];   // [N,3]
    const float* theta  = (const float*)d_in[1];   // [160,160,160,3]
    float* out = (float*)d_out;                    // [N,3]
    int n = in_sizes[0] / 3;

    repack_kernel<<<GRID_R * GRID_R, GRID_R>>>(theta);

    int threads = 256;
    int pairs = (n + 1) / 2;
    int blocks = (pairs + threads - 1) / threads;
    trilerp_kernel<<<blocks, threads>>>(coords, out, n);
}

// round 11
// speedup vs baseline: 1.0008x; 1.0008x over previous
#include <cuda_runtime.h>
#include <cuda_fp16.h>

// DeformationGrid: trilinear interpolation of a [160,160,160,3] float grid
// at N=4194304 random points in the unit cube.
//
// R9 = R8 resubmitted after broker-side infra failure (no code change).
//
// R8: revert to the proven R4 shape (1 point/thread, 4 LDG.128 z-pair
// gathers — the 2-pts/thread variant serialized its gathers under register
// pressure and regressed). New: cache-policy isolation. R4's ncu showed
// 268MB of DRAM traffic vs 96MB of mandatory streams — the 65.5MB grid was
// being evicted by the coord/out streams and refetched ~2.6x. So:
//   coords  -> __ldcs (evict-first streaming read)
//   gathers -> __ldcg (L2-only; L1 hit rate on 65.5MB random is ~0)
//   out     -> __stcs (streaming store)

#define GRID_R 160
#define NVOX (GRID_R * GRID_R * GRID_R)   // 4,096,000

// 16B z-pair entry: halves [c0z0,c1z0, c2z0,c0z1, c1z1,c2z1, pad]
__device__ uint4 g_pair[NVOX];            // 65.5 MB scratch (.bss — allowed)

__device__ __forceinline__ unsigned h2_to_u32(__half2 h) {
    return *reinterpret_cast<unsigned*>(&h);
}
__device__ __forceinline__ __half2 u32_to_h2(unsigned u) {
    return *reinterpret_cast<__half2*>(&u);
}

// ---------------------------------------------------------------------------
// Repack: one block per (x,y) row of 160 z-voxels. Coalesced.
// ---------------------------------------------------------------------------
__global__ void __launch_bounds__(160)
repack_kernel(const float* __restrict__ theta)
{
    __shared__ float s[480];
    int row = blockIdx.x;                  // x*160 + y
    int t = threadIdx.x;                   // 0..159
    const float* src = theta + (size_t)row * 480;
    s[t]       = __ldg(src + t);
    s[t + 160] = __ldg(src + t + 160);
    s[t + 320] = __ldg(src + t + 320);
    __syncthreads();

    int z1 = min(t + 1, GRID_R - 1);       // z=159 entry: weight-0 duplicate
    uint4 e;
    e.x = h2_to_u32(__floats2half2_rn(s[3 * t + 0], s[3 * t + 1]));
    e.y = h2_to_u32(__floats2half2_rn(s[3 * t + 2], s[3 * z1 + 0]));
    e.z = h2_to_u32(__floats2half2_rn(s[3 * z1 + 1], s[3 * z1 + 2]));
    e.w = 0u;
    g_pair[(size_t)row * GRID_R + t] = e;
}

// ---------------------------------------------------------------------------
// Gather: one thread per point, 4 LDG.128 L2-only gathers, fused lerps.
// ---------------------------------------------------------------------------
__device__ __forceinline__ float flerp(float a, float b, float t) {
    return fmaf(t, b - a, a);
}

__device__ __forceinline__ void zlerp_entry(uint4 e, float fz,
                                            float& r0, float& r1, float& r2)
{
    float2 p0 = __half22float2(u32_to_h2(e.x));   // (c0z0, c1z0)
    float2 p1 = __half22float2(u32_to_h2(e.y));   // (c2z0, c0z1)
    float2 p2 = __half22float2(u32_to_h2(e.z));   // (c1z1, c2z1)
    r0 = flerp(p0.x, p1.y, fz);
    r1 = flerp(p0.y, p2.x, fz);
    r2 = flerp(p1.x, p2.y, fz);
}

__global__ void __launch_bounds__(256)
trilerp_kernel(const float* __restrict__ coords,
               float* __restrict__ out,
               int n)
{
    int i = blockIdx.x * blockDim.x + threadIdx.x;
    if (i >= n) return;

    // Streaming coord reads (evict-first; don't displace the grid in L2).
    float cx = __ldcs(coords + 3 * i + 0);
    float cy = __ldcs(coords + 3 * i + 1);
    float cz = __ldcs(coords + 3 * i + 2);

    const float scale = (float)(GRID_R - 1);   // 159
    float px = cx * scale, py = cy * scale, pz = cz * scale;

    float fx0 = floorf(px), fy0 = floorf(py), fz0 = floorf(pz);
    float fx = px - fx0, fy = py - fy0, fz = pz - fz0;

    int ix = (int)fx0, iy = (int)fy0, iz = (int)fz0;
    // Safety clamps. In-range coords: no-ops. Upper boundary: the +1 corner
    // has weight 0, so replicate-clamp matches cval=0 semantics.
    ix = min(max(ix, 0), GRID_R - 1);
    iy = min(max(iy, 0), GRID_R - 1);
    iz = min(max(iz, 0), GRID_R - 1);
    int ix1 = min(ix + 1, GRID_R - 1);
    int iy1 = min(iy + 1, GRID_R - 1);

    const int SX = GRID_R * GRID_R;
    const int SY = GRID_R;

    int b00 = ix  * SX + iy  * SY + iz;
    int b01 = ix  * SX + iy1 * SY + iz;
    int b10 = ix1 * SX + iy  * SY + iz;
    int b11 = ix1 * SX + iy1 * SY + iz;

    // 4 gathers (L2-only), each returns both z-corners for one (x,y) combo.
    uint4 e00 = __ldcg(g_pair + b00);
    uint4 e01 = __ldcg(g_pair + b01);
    uint4 e10 = __ldcg(g_pair + b10);
    uint4 e11 = __ldcg(g_pair + b11);

    float c00x, c00y, c00z, c01x, c01y, c01z;
    float c10x, c10y, c10z, c11x, c11y, c11z;
    zlerp_entry(e00, fz, c00x, c00y, c00z);
    zlerp_entry(e01, fz, c01x, c01y, c01z);
    zlerp_entry(e10, fz, c10x, c10y, c10z);
    zlerp_entry(e11, fz, c11x, c11y, c11z);

    // lerp along y
    float c0x = flerp(c00x, c01x, fy), c0y = flerp(c00y, c01y, fy), c0z = flerp(c00z, c01z, fy);
    float c1x = flerp(c10x, c11x, fy), c1y = flerp(c10y, c11y, fy), c1z = flerp(c10z, c11z, fy);
    // lerp along x — streaming stores.
    __stcs(out + 3 * i + 0, flerp(c0x, c1x, fx));
    __stcs(out + 3 * i + 1, flerp(c0y, c1y, fx));
    __stcs(out + 3 * i + 2, flerp(c0z, c1z, fx));
}

extern "C" void kernel_launch(void* const* d_in, const int* in_sizes, int n_in,
                              void* d_out, int out_size) {
    const float* coords = (const float*)d_in[0];   // [N,3]
    const float* theta  = (const float*)d_in[1];   // [160,160,160,3]
    float* out = (float*)d_out;                    // [N,3]
    int n = in_sizes[0] / 3;

    repack_kernel<<<GRID_R * GRID_R, GRID_R>>>(theta);

    int threads = 256;
    int blocks = (n + threads - 1) / threads;
    trilerp_kernel<<<blocks, threads>>>(coords, out, n);
}

// round 13
// speedup vs baseline: 1.4708x; 1.4696x over previous
#include <cuda_runtime.h>
#include <cuda_fp16.h>

// DeformationGrid: trilinear interpolation of a [160,160,160,3] float grid
// at N=4194304 random points in the unit cube.
//
// R11: R4 shape (1 point/thread, 4 LDG.128 z-pair gathers via __ldg —
// R9 proved L1 caching of the gathers is worth ~50% of gather time; the
// aggregate 30MB of L1 holds ~half the 65.5MB grid) + stream cache hints
// ONLY on the pure streams:
//   coords -> __ldcs (evict-first; don't displace grid lines)
//   out    -> __stcs (streaming store)
// R9 confirmed these hints cut DRAM refetch traffic (268MB -> 137MB).

#define GRID_R 160
#define NVOX (GRID_R * GRID_R * GRID_R)   // 4,096,000

// 16B z-pair entry: halves [c0z0,c1z0, c2z0,c0z1, c1z1,c2z1, pad]
__device__ uint4 g_pair[NVOX];            // 65.5 MB scratch (.bss — allowed)

__device__ __forceinline__ unsigned h2_to_u32(__half2 h) {
    return *reinterpret_cast<unsigned*>(&h);
}
__device__ __forceinline__ __half2 u32_to_h2(unsigned u) {
    return *reinterpret_cast<__half2*>(&u);
}

// ---------------------------------------------------------------------------
// Repack: one block per (x,y) row of 160 z-voxels. Coalesced.
// ---------------------------------------------------------------------------
__global__ void __launch_bounds__(160)
repack_kernel(const float* __restrict__ theta)
{
    __shared__ float s[480];
    int row = blockIdx.x;                  // x*160 + y
    int t = threadIdx.x;                   // 0..159
    const float* src = theta + (size_t)row * 480;
    s[t]       = __ldg(src + t);
    s[t + 160] = __ldg(src + t + 160);
    s[t + 320] = __ldg(src + t + 320);
    __syncthreads();

    int z1 = min(t + 1, GRID_R - 1);       // z=159 entry: weight-0 duplicate
    uint4 e;
    e.x = h2_to_u32(__floats2half2_rn(s[3 * t + 0], s[3 * t + 1]));
    e.y = h2_to_u32(__floats2half2_rn(s[3 * t + 2], s[3 * z1 + 0]));
    e.z = h2_to_u32(__floats2half2_rn(s[3 * z1 + 1], s[3 * z1 + 2]));
    e.w = 0u;
    g_pair[(size_t)row * GRID_R + t] = e;
}

// ---------------------------------------------------------------------------
// Gather: one thread per point, 4 LDG.128 cached gathers, fused lerps.
// ---------------------------------------------------------------------------
__device__ __forceinline__ float flerp(float a, float b, float t) {
    return fmaf(t, b - a, a);
}

__device__ __forceinline__ void zlerp_entry(uint4 e, float fz,
                                            float& r0, float& r1, float& r2)
{
    float2 p0 = __half22float2(u32_to_h2(e.x));   // (c0z0, c1z0)
    float2 p1 = __half22float2(u32_to_h2(e.y));   // (c2z0, c0z1)
    float2 p2 = __half22float2(u32_to_h2(e.z));   // (c1z1, c2z1)
    r0 = flerp(p0.x, p1.y, fz);
    r1 = flerp(p0.y, p2.x, fz);
    r2 = flerp(p1.x, p2.y, fz);
}

__global__ void __launch_bounds__(256)
trilerp_kernel(const float* __restrict__ coords,
               float* __restrict__ out,
               int n)
{
    int i = blockIdx.x * blockDim.x + threadIdx.x;
    if (i >= n) return;

    // Streaming coord reads (evict-first; don't displace the grid).
    float cx = __ldcs(coords + 3 * i + 0);
    float cy = __ldcs(coords + 3 * i + 1);
    float cz = __ldcs(coords + 3 * i + 2);

    const float scale = (float)(GRID_R - 1);   // 159
    float px = cx * scale, py = cy * scale, pz = cz * scale;

    float fx0 = floorf(px), fy0 = floorf(py), fz0 = floorf(pz);
    float fx = px - fx0, fy = py - fy0, fz = pz - fz0;

    int ix = (int)fx0, iy = (int)fy0, iz = (int)fz0;
    // Safety clamps. In-range coords: no-ops. Upper boundary: the +1 corner
    // has weight 0, so replicate-clamp matches cval=0 semantics.
    ix = min(max(ix, 0), GRID_R - 1);
    iy = min(max(iy, 0), GRID_R - 1);
    iz = min(max(iz, 0), GRID_R - 1);
    int ix1 = min(ix + 1, GRID_R - 1);
    int iy1 = min(iy + 1, GRID_R - 1);

    const int SX = GRID_R * GRID_R;
    const int SY = GRID_R;

    int b00 = ix  * SX + iy  * SY + iz;
    int b01 = ix  * SX + iy1 * SY + iz;
    int b10 = ix1 * SX + iy  * SY + iz;
    int b11 = ix1 * SX + iy1 * SY + iz;

    // 4 cached gathers, each returns both z-corners for one (x,y) combo.
    uint4 e00 = __ldg(g_pair + b00);
    uint4 e01 = __ldg(g_pair + b01);
    uint4 e10 = __ldg(g_pair + b10);
    uint4 e11 = __ldg(g_pair + b11);

    float c00x, c00y, c00z, c01x, c01y, c01z;
    float c10x, c10y, c10z, c11x, c11y, c11z;
    zlerp_entry(e00, fz, c00x, c00y, c00z);
    zlerp_entry(e01, fz, c01x, c01y, c01z);
    zlerp_entry(e10, fz, c10x, c10y, c10z);
    zlerp_entry(e11, fz, c11x, c11y, c11z);

    // lerp along y
    float c0x = flerp(c00x, c01x, fy), c0y = flerp(c00y, c01y, fy), c0z = flerp(c00z, c01z, fy);
    float c1x = flerp(c10x, c11x, fy), c1y = flerp(c10y, c11y, fy), c1z = flerp(c10z, c11z, fy);
    // lerp along x — streaming stores.
    __stcs(out + 3 * i + 0, flerp(c0x, c1x, fx));
    __stcs(out + 3 * i + 1, flerp(c0y, c1y, fx));
    __stcs(out + 3 * i + 2, flerp(c0z, c1z, fx));
}

extern "C" void kernel_launch(void* const* d_in, const int* in_sizes, int n_in,
                              void* d_out, int out_size) {
    const float* coords = (const float*)d_in[0];   // [N,3]
    const float* theta  = (const float*)d_in[1];   // [160,160,160,3]
    float* out = (float*)d_out;                    // [N,3]
    int n = in_sizes[0] / 3;

    repack_kernel<<<GRID_R * GRID_R, GRID_R>>>(theta);

    int threads = 256;
    int blocks = (n + threads - 1) / threads;
    trilerp_kernel<<<blocks, threads>>>(coords, out, n);
}

// round 15
// speedup vs baseline: 1.5116x; 1.0277x over previous
#include <cuda_runtime.h>
#include <cuda_fp16.h>

// DeformationGrid: trilinear interpolation of a [160,160,160,3] float grid
// at N=4194304 random points in the unit cube.
//
// R13: R4 core (1 point/thread, 4 cached LDG.128 z-pair gathers — the
// proven layout optimum) + shared-memory staging of coords and outputs so
// the stream traffic is fully-coalesced float4 (3 L1 wavefronts per warp
// instead of ~11 each for the strided 12B/point accesses). The gathers are
// wavefront-bound (L1 ~82-88% in all measured variants); this removes the
// only reducible wavefront component.

#define GRID_R 160
#define NVOX (GRID_R * GRID_R * GRID_R)   // 4,096,000
#define TPB 256

// 16B z-pair entry: halves [c0z0,c1z0, c2z0,c0z1, c1z1,c2z1, pad]
__device__ uint4 g_pair[NVOX];            // 65.5 MB scratch (.bss — allowed)

__device__ __forceinline__ unsigned h2_to_u32(__half2 h) {
    return *reinterpret_cast<unsigned*>(&h);
}
__device__ __forceinline__ __half2 u32_to_h2(unsigned u) {
    return *reinterpret_cast<__half2*>(&u);
}

// ---------------------------------------------------------------------------
// Repack: one block per (x,y) row of 160 z-voxels. Coalesced.
// ---------------------------------------------------------------------------
__global__ void __launch_bounds__(160)
repack_kernel(const float* __restrict__ theta)
{
    __shared__ float s[480];
    int row = blockIdx.x;                  // x*160 + y
    int t = threadIdx.x;                   // 0..159
    const float* src = theta + (size_t)row * 480;
    s[t]       = __ldg(src + t);
    s[t + 160] = __ldg(src + t + 160);
    s[t + 320] = __ldg(src + t + 320);
    __syncthreads();

    int z1 = min(t + 1, GRID_R - 1);       // z=159 entry: weight-0 duplicate
    uint4 e;
    e.x = h2_to_u32(__floats2half2_rn(s[3 * t + 0], s[3 * t + 1]));
    e.y = h2_to_u32(__floats2half2_rn(s[3 * t + 2], s[3 * z1 + 0]));
    e.z = h2_to_u32(__floats2half2_rn(s[3 * z1 + 1], s[3 * z1 + 2]));
    e.w = 0u;
    g_pair[(size_t)row * GRID_R + t] = e;
}

// ---------------------------------------------------------------------------
// Gather: one thread per point; coords/outs staged via smem (coalesced
// float4), 4 cached LDG.128 gathers, fused lerps.
// ---------------------------------------------------------------------------
__device__ __forceinline__ float flerp(float a, float b, float t) {
    return fmaf(t, b - a, a);
}

__device__ __forceinline__ void zlerp_entry(uint4 e, float fz,
                                            float& r0, float& r1, float& r2)
{
    float2 p0 = __half22float2(u32_to_h2(e.x));   // (c0z0, c1z0)
    float2 p1 = __half22float2(u32_to_h2(e.y));   // (c2z0, c0z1)
    float2 p2 = __half22float2(u32_to_h2(e.z));   // (c1z1, c2z1)
    r0 = flerp(p0.x, p1.y, fz);
    r1 = flerp(p0.y, p2.x, fz);
    r2 = flerp(p1.x, p2.y, fz);
}

__global__ void __launch_bounds__(TPB)
trilerp_kernel(const float* __restrict__ coords,
               float* __restrict__ out,
               int n)
{
    __shared__ float s[TPB * 3];           // 3 KB staging buffer
    int t = threadIdx.x;
    int blockBase = blockIdx.x * TPB;      // first point of this block
    int i = blockBase + t;
    bool fullBlock = (blockBase + TPB <= n);

    float cx, cy, cz;
    if (fullBlock) {
        // Coalesced stage-in: 3*TPB floats = (3*TPB/4) float4 loads.
        const float4* c4 = (const float4*)(coords + (size_t)blockBase * 3);
        float4* s4 = (float4*)s;
        if (t < (TPB * 3) / 4) s4[t] = __ldg(c4 + t);
        __syncthreads();
        cx = s[3 * t + 0];                 // stride-3: bank-conflict-free
        cy = s[3 * t + 1];
        cz = s[3 * t + 2];
    } else {
        if (i >= n) return;
        cx = __ldg(coords + 3 * i + 0);
        cy = __ldg(coords + 3 * i + 1);
        cz = __ldg(coords + 3 * i + 2);
    }

    const float scale = (float)(GRID_R - 1);   // 159
    float px = cx * scale, py = cy * scale, pz = cz * scale;

    float fx0 = floorf(px), fy0 = floorf(py), fz0 = floorf(pz);
    float fx = px - fx0, fy = py - fy0, fz = pz - fz0;

    int ix = (int)fx0, iy = (int)fy0, iz = (int)fz0;
    // Safety clamps. In-range coords: no-ops. Upper boundary: the +1 corner
    // has weight 0, so replicate-clamp matches cval=0 semantics.
    ix = min(max(ix, 0), GRID_R - 1);
    iy = min(max(iy, 0), GRID_R - 1);
    iz = min(max(iz, 0), GRID_R - 1);
    int ix1 = min(ix + 1, GRID_R - 1);
    int iy1 = min(iy + 1, GRID_R - 1);

    const int SX = GRID_R * GRID_R;
    const int SY = GRID_R;

    int b00 = ix  * SX + iy  * SY + iz;
    int b01 = ix  * SX + iy1 * SY + iz;
    int b10 = ix1 * SX + iy  * SY + iz;
    int b11 = ix1 * SX + iy1 * SY + iz;

    // 4 cached gathers, each returns both z-corners for one (x,y) combo.
    uint4 e00 = __ldg(g_pair + b00);
    uint4 e01 = __ldg(g_pair + b01);
    uint4 e10 = __ldg(g_pair + b10);
    uint4 e11 = __ldg(g_pair + b11);

    float c00x, c00y, c00z, c01x, c01y, c01z;
    float c10x, c10y, c10z, c11x, c11y, c11z;
    zlerp_entry(e00, fz, c00x, c00y, c00z);
    zlerp_entry(e01, fz, c01x, c01y, c01z);
    zlerp_entry(e10, fz, c10x, c10y, c10z);
    zlerp_entry(e11, fz, c11x, c11y, c11z);

    float c0x = flerp(c00x, c01x, fy), c0y = flerp(c00y, c01y, fy), c0z = flerp(c00z, c01z, fy);
    float c1x = flerp(c10x, c11x, fy), c1y = flerp(c10y, c11y, fy), c1z = flerp(c10z, c11z, fy);
    float rx = flerp(c0x, c1x, fx);
    float ry = flerp(c0y, c1y, fx);
    float rz = flerp(c0z, c1z, fx);

    if (fullBlock) {
        // Stage-out then coalesced float4 streaming stores.
        __syncthreads();                   // coords reads done; reuse s
        s[3 * t + 0] = rx;
        s[3 * t + 1] = ry;
        s[3 * t + 2] = rz;
        __syncthreads();
        float4* o4 = (float4*)(out + (size_t)blockBase * 3);
        const float4* s4 = (const float4*)s;
        if (t < (TPB * 3) / 4) __stcs(o4 + t, s4[t]);
    } else {
        out[3 * i + 0] = rx;
        out[3 * i + 1] = ry;
        out[3 * i + 2] = rz;
    }
}

extern "C" void kernel_launch(void* const* d_in, const int* in_sizes, int n_in,
                              void* d_out, int out_size) {
    const float* coords = (const float*)d_in[0];   // [N,3]
    const float* theta  = (const float*)d_in[1];   // [160,160,160,3]
    float* out = (float*)d_out;                    // [N,3]
    int n = in_sizes[0] / 3;

    repack_kernel<<<GRID_R * GRID_R, GRID_R>>>(theta);

    int blocks = (n + TPB - 1) / TPB;
    trilerp_kernel<<<blocks, TPB>>>(coords, out, n);
}